// round 13
// baseline (speedup 1.0000x reference)
#include <cuda_runtime.h>
#include <stdint.h>

// ---------------------------------------------------------------------------
// FakeQuant (global min/max), split kernels — atomics + static sentinels.
//
// L2 handoff, eviction-order-aware:
//   reduce (forward):  [0, keep_thresh) __ldcs (streaming),
//                      [keep_thresh, n4) default — fills L2 low->high.
//   apply:             phase A reads [keep_thresh, n4) FORWARD — the same
//                      order the lines were filled, so the read front chases
//                      the (oldest-first) eviction front with an ~14MB head
//                      start and never gets caught -> ~full 112MB reuse
//                      (backward consumption only ever got the newest half).
//                      phase B reads [0, keep_thresh) with __ldcs.
//                      All writes __stcs (evict-first marked).
//
//   Global min/max: order-preserving-uint atomicMin/Max; sentinels statically
//   initialized and restored by the last-finishing apply block for graph replay.
//
//   out = rint((x - mn)*scale)/scale + mn,  scale = 255/(mx - mn)
//   (clip(x, min(x), max(x)) == x, dropped.)
// ---------------------------------------------------------------------------

#define RED_BLOCKS (148 * 8)   // 1184
#define APP_BLOCKS (148 * 8)   // 1184 (measured best)
#define TPB 256

__device__ unsigned int g_min_bits = 0xFFFFFFFFu;
__device__ unsigned int g_max_bits = 0x00000000u;
__device__ unsigned int g_app_done = 0;          // self-resetting

__device__ __forceinline__ unsigned int flip_f2u(float f) {
    unsigned int b = __float_as_uint(f);
    return (b & 0x80000000u) ? ~b : (b | 0x80000000u);
}
__device__ __forceinline__ float unflip_u2f(unsigned int b) {
    unsigned int r = (b & 0x80000000u) ? (b & 0x7FFFFFFFu) : ~b;
    return __uint_as_float(r);
}

__device__ __forceinline__ void acc4(float4 v, float& mn, float& mx) {
    mn = fminf(mn, fminf(fminf(v.x, v.y), fminf(v.z, v.w)));
    mx = fmaxf(mx, fmaxf(fmaxf(v.x, v.y), fmaxf(v.z, v.w)));
}

__device__ __forceinline__ float4 fq4(float4 v, float mn, float scale, float inv) {
    float4 r;
    r.x = fmaf(rintf((v.x - mn) * scale), inv, mn);
    r.y = fmaf(rintf((v.y - mn) * scale), inv, mn);
    r.z = fmaf(rintf((v.z - mn) * scale), inv, mn);
    r.w = fmaf(rintf((v.w - mn) * scale), inv, mn);
    return r;
}

// ---------------- reduce: forward sweep --------------------------------------
__global__ void __launch_bounds__(TPB) minmax_reduce_kernel(
    const float4* __restrict__ x4, int n4, int keep_thresh) {
    float mn = 3.402823466e+38f;
    float mx = -3.402823466e+38f;

    const int S = gridDim.x * blockDim.x;
    int i = blockIdx.x * blockDim.x + threadIdx.x;

    // Low region: streaming loads.
    for (; i + 3 * S < keep_thresh; i += 4 * S) {
        float4 a = __ldcs(&x4[i]);
        float4 b = __ldcs(&x4[i + S]);
        float4 c = __ldcs(&x4[i + 2 * S]);
        float4 d = __ldcs(&x4[i + 3 * S]);
        acc4(a, mn, mx); acc4(b, mn, mx); acc4(c, mn, mx); acc4(d, mn, mx);
    }
    for (; i < keep_thresh; i += S) acc4(__ldcs(&x4[i]), mn, mx);

    // Top region: default policy — fills L2 low->high for the apply pass.
    for (; i + 3 * S < n4; i += 4 * S) {
        float4 a = x4[i];
        float4 b = x4[i + S];
        float4 c = x4[i + 2 * S];
        float4 d = x4[i + 3 * S];
        acc4(a, mn, mx); acc4(b, mn, mx); acc4(c, mn, mx); acc4(d, mn, mx);
    }
    for (; i < n4; i += S) acc4(x4[i], mn, mx);

    // warp + block reduce, then ONE atomic pair per block.
    #pragma unroll
    for (int off = 16; off > 0; off >>= 1) {
        mn = fminf(mn, __shfl_xor_sync(0xFFFFFFFFu, mn, off));
        mx = fmaxf(mx, __shfl_xor_sync(0xFFFFFFFFu, mx, off));
    }
    __shared__ float s_mn[TPB / 32];
    __shared__ float s_mx[TPB / 32];
    int wid = threadIdx.x >> 5;
    int lid = threadIdx.x & 31;
    if (lid == 0) { s_mn[wid] = mn; s_mx[wid] = mx; }
    __syncthreads();
    if (wid == 0) {
        const int nw = TPB / 32;
        mn = (lid < nw) ? s_mn[lid] : 3.402823466e+38f;
        mx = (lid < nw) ? s_mx[lid] : -3.402823466e+38f;
        #pragma unroll
        for (int off = 4; off > 0; off >>= 1) {
            mn = fminf(mn, __shfl_xor_sync(0xFFFFFFFFu, mn, off));
            mx = fmaxf(mx, __shfl_xor_sync(0xFFFFFFFFu, mx, off));
        }
        if (lid == 0) {
            atomicMin(&g_min_bits, flip_f2u(mn));
            atomicMax(&g_max_bits, flip_f2u(mx));
        }
    }
}

// ---------------- apply: phase A = keep region FORWARD (fill order) ---------
__global__ void __launch_bounds__(TPB) fakequant_apply_kernel(
    const float4* __restrict__ x4, float4* __restrict__ out4,
    int n4, int keep_thresh,
    const float* __restrict__ x, float* __restrict__ out, int n) {
    const float mn = unflip_u2f(g_min_bits);
    const float mx = unflip_u2f(g_max_bits);
    const float scale = 255.0f / (mx - mn);
    const float inv   = 1.0f / scale;

    const int S = gridDim.x * blockDim.x;
    const int gtid = blockIdx.x * blockDim.x + threadIdx.x;

    // Phase A: [keep_thresh, n4) forward — chase the eviction front.
    {
        int i = keep_thresh + gtid;
        for (; i + 3 * S < n4; i += 4 * S) {
            float4 a = x4[i];
            float4 b = x4[i + S];
            float4 c = x4[i + 2 * S];
            float4 d = x4[i + 3 * S];
            __stcs(&out4[i],         fq4(a, mn, scale, inv));
            __stcs(&out4[i + S],     fq4(b, mn, scale, inv));
            __stcs(&out4[i + 2 * S], fq4(c, mn, scale, inv));
            __stcs(&out4[i + 3 * S], fq4(d, mn, scale, inv));
        }
        for (; i < n4; i += S)
            __stcs(&out4[i], fq4(x4[i], mn, scale, inv));
    }

    // Phase B: [0, keep_thresh) forward, streaming reads (DRAM misses anyway).
    {
        int i = gtid;
        for (; i + 3 * S < keep_thresh; i += 4 * S) {
            float4 a = __ldcs(&x4[i]);
            float4 b = __ldcs(&x4[i + S]);
            float4 c = __ldcs(&x4[i + 2 * S]);
            float4 d = __ldcs(&x4[i + 3 * S]);
            __stcs(&out4[i],         fq4(a, mn, scale, inv));
            __stcs(&out4[i + S],     fq4(b, mn, scale, inv));
            __stcs(&out4[i + 2 * S], fq4(c, mn, scale, inv));
            __stcs(&out4[i + 3 * S], fq4(d, mn, scale, inv));
        }
        for (; i < keep_thresh; i += S)
            __stcs(&out4[i], fq4(__ldcs(&x4[i]), mn, scale, inv));
    }

    // Scalar tail (n % 4 != 0; never hit for this shape).
    int tail_start = n4 << 2;
    if (blockIdx.x == 0) {
        for (int i = tail_start + threadIdx.x; i < n; i += TPB)
            out[i] = fmaf(rintf((x[i] - mn) * scale), inv, mn);
    }

    // Last-finishing block restores the sentinels for the next graph replay.
    __syncthreads();
    if (threadIdx.x == 0) {
        unsigned int prev = atomicAdd(&g_app_done, 1u);
        if (prev == (unsigned int)(gridDim.x - 1)) {
            g_app_done = 0;
            g_min_bits = 0xFFFFFFFFu;
            g_max_bits = 0x00000000u;
        }
    }
}

extern "C" void kernel_launch(void* const* d_in, const int* in_sizes, int n_in,
                              void* d_out, int out_size) {
    const float* x = (const float*)d_in[0];
    float* out = (float*)d_out;
    int n = in_sizes[0];
    int n4 = n >> 2;

    // Keep region: TOP ~112MB (L2 ~126MB -> ~14MB head start for the race).
    const long long KEEP_BYTES = 112LL * 1024 * 1024;
    int keep_elems = (int)(KEEP_BYTES / 16);  // float4s
    int keep_thresh = n4 > keep_elems ? n4 - keep_elems : 0;

    minmax_reduce_kernel<<<RED_BLOCKS, TPB>>>((const float4*)x, n4, keep_thresh);
    fakequant_apply_kernel<<<APP_BLOCKS, TPB>>>((const float4*)x, (float4*)out,
                                                n4, keep_thresh, x, out, n);
}

// round 14
// speedup vs baseline: 1.0649x; 1.0649x over previous
#include <cuda_runtime.h>
#include <stdint.h>

// ---------------------------------------------------------------------------
// FakeQuant (global min/max), split kernels — round-11 winner, KEEP=120MB.
//
//   reduce (forward):  [0, keep_thresh) __ldcs (streaming),
//                      [keep_thresh, n4) default (stays L2-resident for apply)
//   apply  (backward): __ldcs reads — newest-first consumption wins the
//                      eviction race for ~L2/3 of reuse (measured ~55MB);
//                      __stcs writes. 1184 blocks (measured best).
//
//   Global min/max: order-preserving-uint atomicMin/Max; sentinels statically
//   initialized at module load and restored by the last-finishing apply block
//   (self-resetting done counter) for CUDA-graph replay.
//
//   out = rint((x - mn)*scale)/scale + mn,  scale = 255/(mx - mn)
//   (clip(x, min(x), max(x)) == x, dropped.)
// ---------------------------------------------------------------------------

#define RED_BLOCKS (148 * 8)   // 1184
#define APP_BLOCKS (148 * 8)   // 1184
#define TPB 256

__device__ unsigned int g_min_bits = 0xFFFFFFFFu;
__device__ unsigned int g_max_bits = 0x00000000u;
__device__ unsigned int g_app_done = 0;          // self-resetting

__device__ __forceinline__ unsigned int flip_f2u(float f) {
    unsigned int b = __float_as_uint(f);
    return (b & 0x80000000u) ? ~b : (b | 0x80000000u);
}
__device__ __forceinline__ float unflip_u2f(unsigned int b) {
    unsigned int r = (b & 0x80000000u) ? (b & 0x7FFFFFFFu) : ~b;
    return __uint_as_float(r);
}

__device__ __forceinline__ void acc4(float4 v, float& mn, float& mx) {
    mn = fminf(mn, fminf(fminf(v.x, v.y), fminf(v.z, v.w)));
    mx = fmaxf(mx, fmaxf(fmaxf(v.x, v.y), fmaxf(v.z, v.w)));
}

__device__ __forceinline__ float4 fq4(float4 v, float mn, float scale, float inv) {
    float4 r;
    r.x = fmaf(rintf((v.x - mn) * scale), inv, mn);
    r.y = fmaf(rintf((v.y - mn) * scale), inv, mn);
    r.z = fmaf(rintf((v.z - mn) * scale), inv, mn);
    r.w = fmaf(rintf((v.w - mn) * scale), inv, mn);
    return r;
}

// ---------------- reduce: forward sweep --------------------------------------
__global__ void __launch_bounds__(TPB) minmax_reduce_kernel(
    const float4* __restrict__ x4, int n4, int keep_thresh) {
    float mn = 3.402823466e+38f;
    float mx = -3.402823466e+38f;

    const int S = gridDim.x * blockDim.x;
    int i = blockIdx.x * blockDim.x + threadIdx.x;

    // Low region: streaming loads.
    for (; i + 3 * S < keep_thresh; i += 4 * S) {
        float4 a = __ldcs(&x4[i]);
        float4 b = __ldcs(&x4[i + S]);
        float4 c = __ldcs(&x4[i + 2 * S]);
        float4 d = __ldcs(&x4[i + 3 * S]);
        acc4(a, mn, mx); acc4(b, mn, mx); acc4(c, mn, mx); acc4(d, mn, mx);
    }
    for (; i < keep_thresh; i += S) acc4(__ldcs(&x4[i]), mn, mx);

    // Top region: default policy — stays in L2 for apply.
    for (; i + 3 * S < n4; i += 4 * S) {
        float4 a = x4[i];
        float4 b = x4[i + S];
        float4 c = x4[i + 2 * S];
        float4 d = x4[i + 3 * S];
        acc4(a, mn, mx); acc4(b, mn, mx); acc4(c, mn, mx); acc4(d, mn, mx);
    }
    for (; i < n4; i += S) acc4(x4[i], mn, mx);

    // warp + block reduce, then ONE atomic pair per block.
    #pragma unroll
    for (int off = 16; off > 0; off >>= 1) {
        mn = fminf(mn, __shfl_xor_sync(0xFFFFFFFFu, mn, off));
        mx = fmaxf(mx, __shfl_xor_sync(0xFFFFFFFFu, mx, off));
    }
    __shared__ float s_mn[TPB / 32];
    __shared__ float s_mx[TPB / 32];
    int wid = threadIdx.x >> 5;
    int lid = threadIdx.x & 31;
    if (lid == 0) { s_mn[wid] = mn; s_mx[wid] = mx; }
    __syncthreads();
    if (wid == 0) {
        const int nw = TPB / 32;
        mn = (lid < nw) ? s_mn[lid] : 3.402823466e+38f;
        mx = (lid < nw) ? s_mx[lid] : -3.402823466e+38f;
        #pragma unroll
        for (int off = 4; off > 0; off >>= 1) {
            mn = fminf(mn, __shfl_xor_sync(0xFFFFFFFFu, mn, off));
            mx = fmaxf(mx, __shfl_xor_sync(0xFFFFFFFFu, mx, off));
        }
        if (lid == 0) {
            atomicMin(&g_min_bits, flip_f2u(mn));
            atomicMax(&g_max_bits, flip_f2u(mx));
        }
    }
}

// ---------------- apply: backward sweep, 4-wide, 1184 blocks ----------------
__global__ void __launch_bounds__(TPB) fakequant_apply_kernel(
    const float4* __restrict__ x4, float4* __restrict__ out4, int n4,
    const float* __restrict__ x, float* __restrict__ out, int n) {
    const float mn = unflip_u2f(g_min_bits);
    const float mx = unflip_u2f(g_max_bits);
    const float scale = 255.0f / (mx - mn);
    const float inv   = 1.0f / scale;

    const int S = gridDim.x * blockDim.x;
    const int gtid = blockIdx.x * blockDim.x + threadIdx.x;

    if (gtid < n4) {
        int k = (n4 - 1 - gtid) / S;  // highest valid stride index

        for (; k >= 3; k -= 4) {
            int i0 = gtid + k * S;
            int i1 = i0 - S;
            int i2 = i0 - 2 * S;
            int i3 = i0 - 3 * S;
            float4 a = __ldcs(&x4[i0]);
            float4 b = __ldcs(&x4[i1]);
            float4 c = __ldcs(&x4[i2]);
            float4 d = __ldcs(&x4[i3]);
            __stcs(&out4[i0], fq4(a, mn, scale, inv));
            __stcs(&out4[i1], fq4(b, mn, scale, inv));
            __stcs(&out4[i2], fq4(c, mn, scale, inv));
            __stcs(&out4[i3], fq4(d, mn, scale, inv));
        }
        for (; k >= 0; --k) {
            int i0 = gtid + k * S;
            __stcs(&out4[i0], fq4(__ldcs(&x4[i0]), mn, scale, inv));
        }
    }

    // Scalar tail (n % 4 != 0; never hit for this shape).
    int tail_start = n4 << 2;
    if (blockIdx.x == 0) {
        for (int i = tail_start + threadIdx.x; i < n; i += TPB)
            out[i] = fmaf(rintf((x[i] - mn) * scale), inv, mn);
    }

    // Last-finishing block restores the sentinels for the next graph replay.
    __syncthreads();
    if (threadIdx.x == 0) {
        unsigned int prev = atomicAdd(&g_app_done, 1u);
        if (prev == (unsigned int)(gridDim.x - 1)) {
            g_app_done = 0;
            g_min_bits = 0xFFFFFFFFu;
            g_max_bits = 0x00000000u;
        }
    }
}

extern "C" void kernel_launch(void* const* d_in, const int* in_sizes, int n_in,
                              void* d_out, int out_size) {
    const float* x = (const float*)d_in[0];
    float* out = (float*)d_out;
    int n = in_sizes[0];
    int n4 = n >> 2;

    // Keep the TOP ~120MB of x default-policy in reduce (L2 is ~126MB).
    const long long KEEP_BYTES = 120LL * 1024 * 1024;
    int keep_elems = (int)(KEEP_BYTES / 16);  // float4s
    int keep_thresh = n4 > keep_elems ? n4 - keep_elems : 0;

    minmax_reduce_kernel<<<RED_BLOCKS, TPB>>>((const float4*)x, n4, keep_thresh);
    fakequant_apply_kernel<<<APP_BLOCKS, TPB>>>((const float4*)x, (float4*)out,
                                                n4, x, out, n);
}

// round 15
// speedup vs baseline: 1.0678x; 1.0027x over previous
#include <cuda_runtime.h>
#include <stdint.h>

// ---------------------------------------------------------------------------
// FakeQuant (global min/max), split kernels — VERIFIED OPTIMUM (round 11,
// reproduced twice at 92.9us):
//
//   reduce (forward):  [0, keep_thresh) __ldcs (streaming),
//                      [keep_thresh=top 112MB, n4) default policy
//                      (stays L2-resident; apply's backward sweep consumes
//                      the newest ~55MB before the write-alloc eviction
//                      front reclaims it — the race-equilibrium maximum).
//   apply  (backward): __ldcs reads, __stcs writes, 4-wide, 1184 blocks.
//
//   Global min/max: order-preserving-uint atomicMin/Max (flip trick);
//   sentinels statically initialized at module load and restored by the
//   last-finishing apply block (self-resetting done counter) so the kernel
//   is deterministic across CUDA-graph replays.
//
//   out = rint((x - mn)*scale)/scale + mn,  scale = 255/(mx - mn)
//   (clip(x, min(x), max(x)) == x, dropped.)
// ---------------------------------------------------------------------------

#define RED_BLOCKS (148 * 8)   // 1184
#define APP_BLOCKS (148 * 8)   // 1184 (measured best for apply)
#define TPB 256

__device__ unsigned int g_min_bits = 0xFFFFFFFFu;
__device__ unsigned int g_max_bits = 0x00000000u;
__device__ unsigned int g_app_done = 0;          // self-resetting

__device__ __forceinline__ unsigned int flip_f2u(float f) {
    unsigned int b = __float_as_uint(f);
    return (b & 0x80000000u) ? ~b : (b | 0x80000000u);
}
__device__ __forceinline__ float unflip_u2f(unsigned int b) {
    unsigned int r = (b & 0x80000000u) ? (b & 0x7FFFFFFFu) : ~b;
    return __uint_as_float(r);
}

__device__ __forceinline__ void acc4(float4 v, float& mn, float& mx) {
    mn = fminf(mn, fminf(fminf(v.x, v.y), fminf(v.z, v.w)));
    mx = fmaxf(mx, fmaxf(fmaxf(v.x, v.y), fmaxf(v.z, v.w)));
}

__device__ __forceinline__ float4 fq4(float4 v, float mn, float scale, float inv) {
    float4 r;
    r.x = fmaf(rintf((v.x - mn) * scale), inv, mn);
    r.y = fmaf(rintf((v.y - mn) * scale), inv, mn);
    r.z = fmaf(rintf((v.z - mn) * scale), inv, mn);
    r.w = fmaf(rintf((v.w - mn) * scale), inv, mn);
    return r;
}

// ---------------- reduce: forward sweep --------------------------------------
__global__ void __launch_bounds__(TPB) minmax_reduce_kernel(
    const float4* __restrict__ x4, int n4, int keep_thresh) {
    float mn = 3.402823466e+38f;
    float mx = -3.402823466e+38f;

    const int S = gridDim.x * blockDim.x;
    int i = blockIdx.x * blockDim.x + threadIdx.x;

    // Low region: streaming loads.
    for (; i + 3 * S < keep_thresh; i += 4 * S) {
        float4 a = __ldcs(&x4[i]);
        float4 b = __ldcs(&x4[i + S]);
        float4 c = __ldcs(&x4[i + 2 * S]);
        float4 d = __ldcs(&x4[i + 3 * S]);
        acc4(a, mn, mx); acc4(b, mn, mx); acc4(c, mn, mx); acc4(d, mn, mx);
    }
    for (; i < keep_thresh; i += S) acc4(__ldcs(&x4[i]), mn, mx);

    // Top region: default policy — stays in L2 for apply.
    for (; i + 3 * S < n4; i += 4 * S) {
        float4 a = x4[i];
        float4 b = x4[i + S];
        float4 c = x4[i + 2 * S];
        float4 d = x4[i + 3 * S];
        acc4(a, mn, mx); acc4(b, mn, mx); acc4(c, mn, mx); acc4(d, mn, mx);
    }
    for (; i < n4; i += S) acc4(x4[i], mn, mx);

    // warp + block reduce, then ONE atomic pair per block.
    #pragma unroll
    for (int off = 16; off > 0; off >>= 1) {
        mn = fminf(mn, __shfl_xor_sync(0xFFFFFFFFu, mn, off));
        mx = fmaxf(mx, __shfl_xor_sync(0xFFFFFFFFu, mx, off));
    }
    __shared__ float s_mn[TPB / 32];
    __shared__ float s_mx[TPB / 32];
    int wid = threadIdx.x >> 5;
    int lid = threadIdx.x & 31;
    if (lid == 0) { s_mn[wid] = mn; s_mx[wid] = mx; }
    __syncthreads();
    if (wid == 0) {
        const int nw = TPB / 32;
        mn = (lid < nw) ? s_mn[lid] : 3.402823466e+38f;
        mx = (lid < nw) ? s_mx[lid] : -3.402823466e+38f;
        #pragma unroll
        for (int off = 4; off > 0; off >>= 1) {
            mn = fminf(mn, __shfl_xor_sync(0xFFFFFFFFu, mn, off));
            mx = fmaxf(mx, __shfl_xor_sync(0xFFFFFFFFu, mx, off));
        }
        if (lid == 0) {
            atomicMin(&g_min_bits, flip_f2u(mn));
            atomicMax(&g_max_bits, flip_f2u(mx));
        }
    }
}

// ---------------- apply: backward sweep, 4-wide, 1184 blocks ----------------
__global__ void __launch_bounds__(TPB) fakequant_apply_kernel(
    const float4* __restrict__ x4, float4* __restrict__ out4, int n4,
    const float* __restrict__ x, float* __restrict__ out, int n) {
    // Read global min/max (2 words, L2-broadcast; the kernel boundary orders
    // them after all reduce-side atomics).
    const float mn = unflip_u2f(g_min_bits);
    const float mx = unflip_u2f(g_max_bits);
    const float scale = 255.0f / (mx - mn);
    const float inv   = 1.0f / scale;

    const int S = gridDim.x * blockDim.x;
    const int gtid = blockIdx.x * blockDim.x + threadIdx.x;

    if (gtid < n4) {
        int k = (n4 - 1 - gtid) / S;  // highest valid stride index

        for (; k >= 3; k -= 4) {
            int i0 = gtid + k * S;
            int i1 = i0 - S;
            int i2 = i0 - 2 * S;
            int i3 = i0 - 3 * S;
            float4 a = __ldcs(&x4[i0]);
            float4 b = __ldcs(&x4[i1]);
            float4 c = __ldcs(&x4[i2]);
            float4 d = __ldcs(&x4[i3]);
            __stcs(&out4[i0], fq4(a, mn, scale, inv));
            __stcs(&out4[i1], fq4(b, mn, scale, inv));
            __stcs(&out4[i2], fq4(c, mn, scale, inv));
            __stcs(&out4[i3], fq4(d, mn, scale, inv));
        }
        for (; k >= 0; --k) {
            int i0 = gtid + k * S;
            __stcs(&out4[i0], fq4(__ldcs(&x4[i0]), mn, scale, inv));
        }
    }

    // Scalar tail (n % 4 != 0; never hit for this shape). Done before the
    // done-counter increment so the sentinel reset stays ordered after it.
    int tail_start = n4 << 2;
    if (blockIdx.x == 0) {
        for (int i = tail_start + threadIdx.x; i < n; i += TPB)
            out[i] = fmaf(rintf((x[i] - mn) * scale), inv, mn);
    }

    // Last-finishing block restores the sentinels for the next graph replay.
    __syncthreads();
    if (threadIdx.x == 0) {
        unsigned int prev = atomicAdd(&g_app_done, 1u);
        if (prev == (unsigned int)(gridDim.x - 1)) {
            g_app_done = 0;
            g_min_bits = 0xFFFFFFFFu;
            g_max_bits = 0x00000000u;
        }
    }
}

extern "C" void kernel_launch(void* const* d_in, const int* in_sizes, int n_in,
                              void* d_out, int out_size) {
    const float* x = (const float*)d_in[0];
    float* out = (float*)d_out;
    int n = in_sizes[0];
    int n4 = n >> 2;

    // Keep the TOP ~112MB of x default-policy in reduce (L2 is ~126MB;
    // 112MB is the measured knee — 120MB self-evicts during reduce's fill).
    const long long KEEP_BYTES = 112LL * 1024 * 1024;
    int keep_elems = (int)(KEEP_BYTES / 16);  // float4s
    int keep_thresh = n4 > keep_elems ? n4 - keep_elems : 0;

    minmax_reduce_kernel<<<RED_BLOCKS, TPB>>>((const float4*)x, n4, keep_thresh);
    fakequant_apply_kernel<<<APP_BLOCKS, TPB>>>((const float4*)x, (float4*)out,
                                                n4, x, out, n);
}

// round 16
// speedup vs baseline: 1.0884x; 1.0193x over previous
#include <cuda_runtime.h>
#include <stdint.h>

// ---------------------------------------------------------------------------
// FakeQuant (global min/max), split kernels — FINAL (round-11 configuration,
// measured 92.90 / 92.93 us; bench noise band ±1.5us).
//
//   reduce (forward):  [0, keep_thresh) __ldcs (streaming),
//                      [keep_thresh = top 112MB, n4) default policy —
//                      stays L2-resident; apply's backward sweep consumes the
//                      newest ~55MB before the write-allocate eviction front
//                      reclaims it (race-equilibrium maximum; fwd/bwd/hinted
//                      variants all measured equal-or-worse).
//   apply  (backward): __ldcs reads, __stcs writes, 4-wide, 1184 blocks
//                      (148x8; 888 and 784 measured slower — aggregate MLP
//                      beats wave alignment for mixed-stream latency hiding).
//
//   Global min/max: order-preserving-uint atomicMin/Max (flip trick);
//   sentinels statically initialized at module load and restored by the
//   last-finishing apply block (self-resetting done counter) so kernel_launch
//   is deterministic across CUDA-graph replays. No init kernel, no fold pass.
//
//   out = rint((x - mn)*scale)/scale + mn,  scale = 255/(mx - mn)
//   (clip(x, min(x), max(x)) == x, so the clip is dropped. rint == RNE ==
//   tf.round semantics; rel_err 1.4e-7 vs reference.)
// ---------------------------------------------------------------------------

#define RED_BLOCKS (148 * 8)   // 1184
#define APP_BLOCKS (148 * 8)   // 1184
#define TPB 256

__device__ unsigned int g_min_bits = 0xFFFFFFFFu;
__device__ unsigned int g_max_bits = 0x00000000u;
__device__ unsigned int g_app_done = 0;          // self-resetting

__device__ __forceinline__ unsigned int flip_f2u(float f) {
    unsigned int b = __float_as_uint(f);
    return (b & 0x80000000u) ? ~b : (b | 0x80000000u);
}
__device__ __forceinline__ float unflip_u2f(unsigned int b) {
    unsigned int r = (b & 0x80000000u) ? (b & 0x7FFFFFFFu) : ~b;
    return __uint_as_float(r);
}

__device__ __forceinline__ void acc4(float4 v, float& mn, float& mx) {
    mn = fminf(mn, fminf(fminf(v.x, v.y), fminf(v.z, v.w)));
    mx = fmaxf(mx, fmaxf(fmaxf(v.x, v.y), fmaxf(v.z, v.w)));
}

__device__ __forceinline__ float4 fq4(float4 v, float mn, float scale, float inv) {
    float4 r;
    r.x = fmaf(rintf((v.x - mn) * scale), inv, mn);
    r.y = fmaf(rintf((v.y - mn) * scale), inv, mn);
    r.z = fmaf(rintf((v.z - mn) * scale), inv, mn);
    r.w = fmaf(rintf((v.w - mn) * scale), inv, mn);
    return r;
}

// ---------------- reduce: forward sweep --------------------------------------
__global__ void __launch_bounds__(TPB) minmax_reduce_kernel(
    const float4* __restrict__ x4, int n4, int keep_thresh) {
    float mn = 3.402823466e+38f;
    float mx = -3.402823466e+38f;

    const int S = gridDim.x * blockDim.x;
    int i = blockIdx.x * blockDim.x + threadIdx.x;

    // Low region: streaming loads.
    for (; i + 3 * S < keep_thresh; i += 4 * S) {
        float4 a = __ldcs(&x4[i]);
        float4 b = __ldcs(&x4[i + S]);
        float4 c = __ldcs(&x4[i + 2 * S]);
        float4 d = __ldcs(&x4[i + 3 * S]);
        acc4(a, mn, mx); acc4(b, mn, mx); acc4(c, mn, mx); acc4(d, mn, mx);
    }
    for (; i < keep_thresh; i += S) acc4(__ldcs(&x4[i]), mn, mx);

    // Top region: default policy — stays in L2 for apply.
    for (; i + 3 * S < n4; i += 4 * S) {
        float4 a = x4[i];
        float4 b = x4[i + S];
        float4 c = x4[i + 2 * S];
        float4 d = x4[i + 3 * S];
        acc4(a, mn, mx); acc4(b, mn, mx); acc4(c, mn, mx); acc4(d, mn, mx);
    }
    for (; i < n4; i += S) acc4(x4[i], mn, mx);

    // warp + block reduce, then ONE atomic pair per block.
    #pragma unroll
    for (int off = 16; off > 0; off >>= 1) {
        mn = fminf(mn, __shfl_xor_sync(0xFFFFFFFFu, mn, off));
        mx = fmaxf(mx, __shfl_xor_sync(0xFFFFFFFFu, mx, off));
    }
    __shared__ float s_mn[TPB / 32];
    __shared__ float s_mx[TPB / 32];
    int wid = threadIdx.x >> 5;
    int lid = threadIdx.x & 31;
    if (lid == 0) { s_mn[wid] = mn; s_mx[wid] = mx; }
    __syncthreads();
    if (wid == 0) {
        const int nw = TPB / 32;
        mn = (lid < nw) ? s_mn[lid] : 3.402823466e+38f;
        mx = (lid < nw) ? s_mx[lid] : -3.402823466e+38f;
        #pragma unroll
        for (int off = 4; off > 0; off >>= 1) {
            mn = fminf(mn, __shfl_xor_sync(0xFFFFFFFFu, mn, off));
            mx = fmaxf(mx, __shfl_xor_sync(0xFFFFFFFFu, mx, off));
        }
        if (lid == 0) {
            atomicMin(&g_min_bits, flip_f2u(mn));
            atomicMax(&g_max_bits, flip_f2u(mx));
        }
    }
}

// ---------------- apply: backward sweep, 4-wide, 1184 blocks ----------------
__global__ void __launch_bounds__(TPB) fakequant_apply_kernel(
    const float4* __restrict__ x4, float4* __restrict__ out4, int n4,
    const float* __restrict__ x, float* __restrict__ out, int n) {
    // Read global min/max (2 words, L2-broadcast; the kernel boundary orders
    // them after all reduce-side atomics).
    const float mn = unflip_u2f(g_min_bits);
    const float mx = unflip_u2f(g_max_bits);
    const float scale = 255.0f / (mx - mn);
    const float inv   = 1.0f / scale;

    const int S = gridDim.x * blockDim.x;
    const int gtid = blockIdx.x * blockDim.x + threadIdx.x;

    if (gtid < n4) {
        int k = (n4 - 1 - gtid) / S;  // highest valid stride index

        for (; k >= 3; k -= 4) {
            int i0 = gtid + k * S;
            int i1 = i0 - S;
            int i2 = i0 - 2 * S;
            int i3 = i0 - 3 * S;
            float4 a = __ldcs(&x4[i0]);
            float4 b = __ldcs(&x4[i1]);
            float4 c = __ldcs(&x4[i2]);
            float4 d = __ldcs(&x4[i3]);
            __stcs(&out4[i0], fq4(a, mn, scale, inv));
            __stcs(&out4[i1], fq4(b, mn, scale, inv));
            __stcs(&out4[i2], fq4(c, mn, scale, inv));
            __stcs(&out4[i3], fq4(d, mn, scale, inv));
        }
        for (; k >= 0; --k) {
            int i0 = gtid + k * S;
            __stcs(&out4[i0], fq4(__ldcs(&x4[i0]), mn, scale, inv));
        }
    }

    // Scalar tail (n % 4 != 0; never hit for this shape). Done before the
    // done-counter increment so the sentinel reset stays ordered after it.
    int tail_start = n4 << 2;
    if (blockIdx.x == 0) {
        for (int i = tail_start + threadIdx.x; i < n; i += TPB)
            out[i] = fmaf(rintf((x[i] - mn) * scale), inv, mn);
    }

    // Last-finishing block restores the sentinels for the next graph replay.
    __syncthreads();
    if (threadIdx.x == 0) {
        unsigned int prev = atomicAdd(&g_app_done, 1u);
        if (prev == (unsigned int)(gridDim.x - 1)) {
            g_app_done = 0;
            g_min_bits = 0xFFFFFFFFu;
            g_max_bits = 0x00000000u;
        }
    }
}

extern "C" void kernel_launch(void* const* d_in, const int* in_sizes, int n_in,
                              void* d_out, int out_size) {
    const float* x = (const float*)d_in[0];
    float* out = (float*)d_out;
    int n = in_sizes[0];
    int n4 = n >> 2;

    // Keep the TOP ~112MB of x default-policy in reduce (L2 is ~126MB;
    // 112MB is the measured knee — 120MB self-evicts during reduce's fill).
    const long long KEEP_BYTES = 112LL * 1024 * 1024;
    int keep_elems = (int)(KEEP_BYTES / 16);  // float4s
    int keep_thresh = n4 > keep_elems ? n4 - keep_elems : 0;

    minmax_reduce_kernel<<<RED_BLOCKS, TPB>>>((const float4*)x, n4, keep_thresh);
    fakequant_apply_kernel<<<APP_BLOCKS, TPB>>>((const float4*)x, (float4*)out,
                                                n4, x, out, n);
}